// round 6
// baseline (speedup 1.0000x reference)
#include <cuda_runtime.h>
#include <cstdint>

#define TPB 256
#define GPB 256  // graphs per block (== TPB, 1 thread per graph)

// Folded constants: v[4][16] (only k<14 used), s[4] @64..67, C @68
__device__ float g_const[80];

// Exactly-rounded 1/sqrt(n) for n = 0..15 (deg in [1,13])
__constant__ float c_rsq[16] = {
    0.0f, 1.0f, 0.70710678118654752f, 0.57735026918962576f,
    0.5f, 0.44721359549995794f, 0.40824829046386302f, 0.37796447300922723f,
    0.35355339059327376f, 0.33333333333333333f, 0.31622776601683794f,
    0.30151134457776363f, 0.28867513459481288f, 0.27735009811261457f,
    0.26726124191242438f, 0.25819888974716110f
};

// ---------------------------------------------------------------------------
// Precompute: collapse the (fully linear) network into 61 floats.
//   M  = (Wl1 Wl2 Wl3 + I + Wl1) Wl4                       [256]
//   c  = bl1·(Wl2 Wl3 Wl4) + bl2·(Wl3 Wl4) + (bl3+bl1)·Wl4 + bl4
//   m_n = M[64n:64n+64], u_n = W2 m_n, v_n = W1 u_n, s_n = b1·u_n
//   C  = c + Σ_n b2·m_n
// ---------------------------------------------------------------------------
__global__ void __launch_bounds__(1024, 1) precompute_kernel(
    const float* __restrict__ W1,  const float* __restrict__ b1,
    const float* __restrict__ W2,  const float* __restrict__ b2,
    const float* __restrict__ Wl1, const float* __restrict__ bl1,
    const float* __restrict__ Wl2, const float* __restrict__ bl2,
    const float* __restrict__ Wl3, const float* __restrict__ bl3,
    const float* __restrict__ Wl4, const float* __restrict__ bl4)
{
    __shared__ float w4s[256], t1s[256], t2s[256], Ms[256];
    __shared__ float us[512];
    __shared__ float part[1024], part2[1024];
    const int t = threadIdx.x;

    if (t < 256) w4s[t] = Wl4[t];
    __syncthreads();

    const int r = t >> 2, q = t & 3;   // 4 threads per output row

    // t1 = Wl3 @ w4
    {
        const float4* row = (const float4*)(Wl3 + r * 256) + q * 16;
        float acc = 0.f;
        #pragma unroll
        for (int j = 0; j < 16; ++j) {
            float4 w = row[j];
            int jb = q * 64 + j * 4;
            acc = fmaf(w.x, w4s[jb+0], acc);
            acc = fmaf(w.y, w4s[jb+1], acc);
            acc = fmaf(w.z, w4s[jb+2], acc);
            acc = fmaf(w.w, w4s[jb+3], acc);
        }
        part[t] = acc;
    }
    __syncthreads();
    if (t < 256) t1s[t] = part[4*t] + part[4*t+1] + part[4*t+2] + part[4*t+3];
    __syncthreads();

    // t2 = Wl2 @ t1
    {
        const float4* row = (const float4*)(Wl2 + r * 256) + q * 16;
        float acc = 0.f;
        #pragma unroll
        for (int j = 0; j < 16; ++j) {
            float4 w = row[j];
            int jb = q * 64 + j * 4;
            acc = fmaf(w.x, t1s[jb+0], acc);
            acc = fmaf(w.y, t1s[jb+1], acc);
            acc = fmaf(w.z, t1s[jb+2], acc);
            acc = fmaf(w.w, t1s[jb+3], acc);
        }
        part[t] = acc;
    }
    __syncthreads();
    if (t < 256) t2s[t] = part[4*t] + part[4*t+1] + part[4*t+2] + part[4*t+3];
    __syncthreads();

    // t3 = Wl1 @ t2 ;  w14 = Wl1 @ w4   (single pass over Wl1)
    {
        const float4* row = (const float4*)(Wl1 + r * 256) + q * 16;
        float a1 = 0.f, a2 = 0.f;
        #pragma unroll
        for (int j = 0; j < 16; ++j) {
            float4 w = row[j];
            int jb = q * 64 + j * 4;
            a1 = fmaf(w.x, t2s[jb+0], a1); a2 = fmaf(w.x, w4s[jb+0], a2);
            a1 = fmaf(w.y, t2s[jb+1], a1); a2 = fmaf(w.y, w4s[jb+1], a2);
            a1 = fmaf(w.z, t2s[jb+2], a1); a2 = fmaf(w.z, w4s[jb+2], a2);
            a1 = fmaf(w.w, t2s[jb+3], a1); a2 = fmaf(w.w, w4s[jb+3], a2);
        }
        part[t] = a1; part2[t] = a2;
    }
    __syncthreads();
    if (t < 256) {
        Ms[t] = (part[4*t] + part[4*t+1] + part[4*t+2] + part[4*t+3])
              + (part2[4*t] + part2[4*t+1] + part2[4*t+2] + part2[4*t+3])
              + w4s[t];
    }
    __syncthreads();

    // scalar bias chain + b2 term; tree-reduce over 256 lanes
    if (t < 256)
        part[t] = bl1[t]*t2s[t] + bl2[t]*t1s[t] + (bl3[t]+bl1[t])*w4s[t]
                + b2[t & 63]*Ms[t];
    else
        part[t] = 0.f;
    __syncthreads();
    #pragma unroll
    for (int s = 128; s > 0; s >>= 1) {
        if (t < s) part[t] += part[t + s];
        __syncthreads();
    }

    // u[n][c] = sum_j W2[c][j] * m_n[j]   (512 outputs)
    if (t < 512) {
        int n = t >> 7, c = t & 127;
        const float4* row = (const float4*)(W2 + c * 64);
        float acc = 0.f;
        #pragma unroll
        for (int j = 0; j < 16; ++j) {
            float4 w = row[j];
            int jb = n * 64 + j * 4;
            acc = fmaf(w.x, Ms[jb+0], acc);
            acc = fmaf(w.y, Ms[jb+1], acc);
            acc = fmaf(w.z, Ms[jb+2], acc);
            acc = fmaf(w.w, Ms[jb+3], acc);
        }
        us[t] = acc;
    }
    __syncthreads();

    if (t < 56) {                        // v[n][k] = sum_c W1[k][c] * u_n[c]
        int n = t / 14, k = t - n * 14;
        const float4* row = (const float4*)(W1 + k * 128);
        float acc = 0.f;
        #pragma unroll
        for (int j = 0; j < 32; ++j) {
            float4 w = row[j];
            int jb = n * 128 + j * 4;
            acc = fmaf(w.x, us[jb+0], acc);
            acc = fmaf(w.y, us[jb+1], acc);
            acc = fmaf(w.z, us[jb+2], acc);
            acc = fmaf(w.w, us[jb+3], acc);
        }
        g_const[n * 16 + k] = acc;
    } else if (t < 60) {                 // s_n = b1 · u_n
        int n = t - 56;
        float acc = 0.f;
        for (int c = 0; c < 128; ++c) acc = fmaf(b1[c], us[n * 128 + c], acc);
        g_const[64 + n] = acc;
    } else if (t == 60) {                // C
        g_const[68] = part[0] + bl4[0];
    }
}

// ---------------------------------------------------------------------------
// Main kernel: 1 thread per graph; coalesced smem staging of x + edges.
// Â is built entirely in registers via nibble-packed edge counting.
// smem (all float4/int4 granules, odd per-graph granule strides):
//   xs4: 256 graphs * 15 float4 @ 0      (61440 B)  writes ~CF STS.128,
//                                                   reads CF LDS.128 (15t+j)
//   es4: 256 graphs *  7 int4   @ 61440  (28672 B)  same trick (7t+j)
//   cs : 80 floats              @ 90112  (  320 B)
// ---------------------------------------------------------------------------
#define SMEM_XS 0
#define SMEM_ES 61440
#define SMEM_CS 90112
#define SMEM_TOTAL 90432

__global__ void __launch_bounds__(TPB, 2) gnn_kernel(
    const float* __restrict__ x, const int* __restrict__ ei,
    float* __restrict__ out)
{
    extern __shared__ unsigned char smem[];
    float4* xs4 = (float4*)(smem + SMEM_XS);
    int4*   es4 = (int4*)(smem + SMEM_ES);
    float*  cs  = (float*)(smem + SMEM_CS);

    const int t = threadIdx.x;
    const long long gbase = (long long)blockIdx.x * GPB;

    if (t < 80) cs[t] = g_const[t];

    // stage x: 256 graphs * 14 float4, fully coalesced loads, padded stores
    const float4* xg = (const float4*)(x + gbase * 56);
    #pragma unroll
    for (int j0 = 0; j0 < 14; ++j0) {
        int i4 = t + j0 * 256;
        float4 v = xg[i4];
        int g = i4 / 14;
        int j = i4 - g * 14;
        xs4[g * 15 + j] = v;
    }
    // stage edges: 256 graphs * 6 int4, coalesced loads, padded stores
    const int4* eg = (const int4*)(ei + gbase * 24);
    #pragma unroll
    for (int j0 = 0; j0 < 6; ++j0) {
        int i4 = t + j0 * 256;
        int4 v = eg[i4];
        int g = i4 / 6;
        int j = i4 - g * 6;
        es4[g * 7 + j] = v;
    }
    __syncthreads();

    // my graph's edges: 6 conflict-free LDS.128
    int me[24];
    #pragma unroll
    for (int j = 0; j < 6; ++j) {
        int4 e = es4[t * 7 + j];
        me[j*4+0] = e.x; me[j*4+1] = e.y; me[j*4+2] = e.z; me[j*4+3] = e.w;
    }

    // --- count edges per (dst,src) pair in packed nibbles (count<=12<16) ---
    unsigned long long accm = 0ull;
    #pragma unroll
    for (int e = 0; e < 12; ++e) {
        int s = me[e];
        int d = me[12 + e];
        accm += 1ull << (((d << 2) + s) << 2);
    }

    // degrees: deg[n] = 1 (self loop) + sum of 4 nibbles of row n
    float dinv[4];
    #pragma unroll
    for (int n = 0; n < 4; ++n) {
        unsigned int rown = (unsigned int)(accm >> (16 * n)) & 0xFFFFu;
        int deg = 1 + (rown & 15) + ((rown >> 4) & 15)
                    + ((rown >> 8) & 15) + ((rown >> 12) & 15);
        dinv[n] = c_rsq[deg];
    }

    // A[n][m] = dinv[n]*dinv[m]*(cnt[n][m] + (n==m))
    float A[16];
    #pragma unroll
    for (int n = 0; n < 4; ++n) {
        #pragma unroll
        for (int m = 0; m < 4; ++m) {
            int cnt = (int)((accm >> (4 * (n * 4 + m))) & 15ull) + (n == m);
            A[n * 4 + m] = dinv[n] * dinv[m] * (float)cnt;
        }
    }

    // acc = C + sum_n rowsum(A)[n] * s_n
    float acc = cs[68];
    #pragma unroll
    for (int n = 0; n < 4; ++n)
        acc = fmaf(A[n*4] + A[n*4+1] + A[n*4+2] + A[n*4+3], cs[64 + n], acc);

    // A2 = A @ A
    float A2[16];
    #pragma unroll
    for (int n = 0; n < 4; ++n) {
        #pragma unroll
        for (int m = 0; m < 4; ++m) {
            A2[n*4+m] = fmaf(A[n*4+0], A[0*4+m],
                        fmaf(A[n*4+1], A[1*4+m],
                        fmaf(A[n*4+2], A[2*4+m], A[n*4+3] * A[3*4+m])));
        }
    }

    // my graph's features: 14 conflict-free LDS.128 (granule 15t+j)
    float xr[56];
    #pragma unroll
    for (int j = 0; j < 14; ++j) {
        float4 v = xs4[t * 15 + j];
        xr[j*4+0] = v.x; xr[j*4+1] = v.y; xr[j*4+2] = v.z; xr[j*4+3] = v.w;
    }

    // acc += sum_{n,k} v_n[k] * (A2 x)[n][k]
    #pragma unroll
    for (int n = 0; n < 4; ++n) {
        #pragma unroll
        for (int k = 0; k < 14; ++k) {
            float y = fmaf(A2[n*4+0], xr[k],
                      fmaf(A2[n*4+1], xr[14+k],
                      fmaf(A2[n*4+2], xr[28+k], A2[n*4+3] * xr[42+k])));
            acc = fmaf(y, cs[n*16 + k], acc);
        }
    }
    out[gbase + t] = acc;
}

// ---------------------------------------------------------------------------
extern "C" void kernel_launch(void* const* d_in, const int* in_sizes, int n_in,
                              void* d_out, int out_size)
{
    const float* x   = (const float*)d_in[0];
    const int*   ei  = (const int*)  d_in[1];
    const float* W1  = (const float*)d_in[2];
    const float* b1  = (const float*)d_in[3];
    const float* W2  = (const float*)d_in[4];
    const float* b2  = (const float*)d_in[5];
    const float* Wl1 = (const float*)d_in[6];
    const float* bl1 = (const float*)d_in[7];
    const float* Wl2 = (const float*)d_in[8];
    const float* bl2 = (const float*)d_in[9];
    const float* Wl3 = (const float*)d_in[10];
    const float* bl3 = (const float*)d_in[11];
    const float* Wl4 = (const float*)d_in[12];
    const float* bl4 = (const float*)d_in[13];

    const int B = in_sizes[0] / 56;          // 262144
    const int nblocks = B / GPB;             // 1024

    precompute_kernel<<<1, 1024>>>(W1, b1, W2, b2, Wl1, bl1, Wl2, bl2,
                                   Wl3, bl3, Wl4, bl4);

    cudaFuncSetAttribute(gnn_kernel,
                         cudaFuncAttributeMaxDynamicSharedMemorySize, SMEM_TOTAL);
    gnn_kernel<<<nblocks, TPB, SMEM_TOTAL>>>(x, ei, (float*)d_out);
}

// round 14
// speedup vs baseline: 2.3700x; 2.3700x over previous
#include <cuda_runtime.h>
#include <cstdint>

#define TPB 256
#define GPB 256  // graphs per block (== TPB, 1 thread per graph)

// Folded constants: v[4][16] (only k<14 used), s[4] @64..67, C @68
__device__ __align__(16) float g_const[80];
// Precompute scratch
__device__ __align__(16) float g_t1[256];
__device__ __align__(16) float g_t2[256];
__device__ __align__(16) float g_Ms[256];
__device__ __align__(16) float g_us[512];

// Exactly-rounded 1/sqrt(n) for n = 0..15 (deg in [1,13])
__constant__ float c_rsq[16] = {
    0.0f, 1.0f, 0.70710678118654752f, 0.57735026918962576f,
    0.5f, 0.44721359549995794f, 0.40824829046386302f, 0.37796447300922723f,
    0.35355339059327376f, 0.33333333333333333f, 0.31622776601683794f,
    0.30151134457776363f, 0.28867513459481288f, 0.27735009811261457f,
    0.26726124191242438f, 0.25819888974716110f
};

// ---------------------------------------------------------------------------
// P1/P2: out[r] = W[r,:] . v   for 256x256 row-major W.  grid=32, block=256.
// ---------------------------------------------------------------------------
__global__ void __launch_bounds__(256) mv256_kernel(
    const float* __restrict__ W, const float* __restrict__ v,
    float* __restrict__ out)
{
    __shared__ float vs[256];
    const int t = threadIdx.x;
    vs[t] = v[t];
    __syncthreads();
    const int row = blockIdx.x * 8 + (t >> 5);
    const int lane = t & 31;
    const float4* wr = (const float4*)(W + row * 256);
    float a = 0.f;
    #pragma unroll
    for (int i = 0; i < 2; ++i) {
        float4 w = wr[lane + 32 * i];
        int c = 4 * (lane + 32 * i);
        a = fmaf(w.x, vs[c+0], fmaf(w.y, vs[c+1],
            fmaf(w.z, vs[c+2], fmaf(w.w, vs[c+3], a))));
    }
    #pragma unroll
    for (int o = 16; o; o >>= 1) a += __shfl_xor_sync(0xFFFFFFFFu, a, o);
    if (lane == 0) out[row] = a;
}

// ---------------------------------------------------------------------------
// P3: Ms[r] = Wl1[r,:].t2 + Wl1[r,:].w4 + w4[r].  grid=32, block=256.
// ---------------------------------------------------------------------------
__global__ void __launch_bounds__(256) mv256_dual_kernel(
    const float* __restrict__ W, const float* __restrict__ v1,
    const float* __restrict__ v2, float* __restrict__ out)
{
    __shared__ float v1s[256], v2s[256];
    const int t = threadIdx.x;
    v1s[t] = v1[t];
    v2s[t] = v2[t];
    __syncthreads();
    const int row = blockIdx.x * 8 + (t >> 5);
    const int lane = t & 31;
    const float4* wr = (const float4*)(W + row * 256);
    float a1 = 0.f, a2 = 0.f;
    #pragma unroll
    for (int i = 0; i < 2; ++i) {
        float4 w = wr[lane + 32 * i];
        int c = 4 * (lane + 32 * i);
        a1 = fmaf(w.x, v1s[c+0], fmaf(w.y, v1s[c+1],
             fmaf(w.z, v1s[c+2], fmaf(w.w, v1s[c+3], a1))));
        a2 = fmaf(w.x, v2s[c+0], fmaf(w.y, v2s[c+1],
             fmaf(w.z, v2s[c+2], fmaf(w.w, v2s[c+3], a2))));
    }
    #pragma unroll
    for (int o = 16; o; o >>= 1) {
        a1 += __shfl_xor_sync(0xFFFFFFFFu, a1, o);
        a2 += __shfl_xor_sync(0xFFFFFFFFu, a2, o);
    }
    if (lane == 0) out[row] = a1 + a2 + v2s[row];
}

// ---------------------------------------------------------------------------
// P4: u[n][c] = W2[c,:] . Ms[64n:64n+64].  grid=8 (b: n=b>>1, chalf=(b&1)*64).
// ---------------------------------------------------------------------------
__global__ void __launch_bounds__(256) u_kernel(const float* __restrict__ W2)
{
    __shared__ __align__(16) float W2s[64 * 17 * 4];  // 64 rows, stride 17 f4
    __shared__ __align__(16) float ms[64];
    __shared__ float part[256];
    const int t = threadIdx.x;
    const int n = blockIdx.x >> 1;
    const int chalf = (blockIdx.x & 1) * 64;

    float4* W2s4 = (float4*)W2s;
    const float4* src = ((const float4*)W2) + chalf * 16;
    #pragma unroll
    for (int i2 = 0; i2 < 4; ++i2) {
        int idx = t + 256 * i2;               // 0..1023
        int c = idx >> 4, i = idx & 15;
        W2s4[c * 17 + i] = src[idx];
    }
    if (t < 16) ((float4*)ms)[t] = ((const float4*)g_Ms)[n * 16 + t];
    __syncthreads();

    const int q = t >> 6, c = t & 63;
    const float4* ms4 = (const float4*)ms;
    float a = 0.f;
    #pragma unroll
    for (int i = 0; i < 4; ++i) {
        float4 w = W2s4[c * 17 + q * 4 + i];
        float4 m = ms4[q * 4 + i];
        a = fmaf(w.x, m.x, fmaf(w.y, m.y, fmaf(w.z, m.z, fmaf(w.w, m.w, a))));
    }
    part[t] = a;
    __syncthreads();
    if (t < 64)
        g_us[n * 128 + chalf + t] =
            part[t] + part[t + 64] + part[t + 128] + part[t + 192];
}

// ---------------------------------------------------------------------------
// P5: v[n][k], s[n], C.  grid=1, block=512.
// ---------------------------------------------------------------------------
__global__ void __launch_bounds__(512) finish_kernel(
    const float* __restrict__ W1,  const float* __restrict__ b1,
    const float* __restrict__ b2,  const float* __restrict__ bl1,
    const float* __restrict__ bl2, const float* __restrict__ bl3,
    const float* __restrict__ Wl4, const float* __restrict__ bl4)
{
    __shared__ __align__(16) float us_s[512];
    __shared__ __align__(16) float W1s[14 * 33 * 4];  // 14 rows, stride 33 f4
    __shared__ float t1s[256], t2s[256], Mss[256], w4s[256];
    __shared__ float part[512];
    const int t = threadIdx.x;

    us_s[t] = g_us[t];
    if (t < 448) ((float4*)W1s)[(t >> 5) * 33 + (t & 31)] = ((const float4*)W1)[t];
    if (t < 256) {
        t1s[t] = g_t1[t]; t2s[t] = g_t2[t];
        Mss[t] = g_Ms[t]; w4s[t] = Wl4[t];
    }
    __syncthreads();

    if (t < 448) {                       // v[n][k], 8 threads per output
        int o = t >> 3, q = t & 7;       // o = n*14 + k
        int n = o / 14, k = o - 14 * n;
        const float4* W1s4 = (const float4*)W1s;
        const float4* us4 = (const float4*)us_s;
        float a = 0.f;
        #pragma unroll
        for (int i = 0; i < 4; ++i) {
            float4 w = W1s4[k * 33 + q * 4 + i];
            float4 u = us4[n * 32 + q * 4 + i];
            a = fmaf(w.x, u.x, fmaf(w.y, u.y, fmaf(w.z, u.z, fmaf(w.w, u.w, a))));
        }
        a += __shfl_xor_sync(0xFFFFFFFFu, a, 1);
        a += __shfl_xor_sync(0xFFFFFFFFu, a, 2);
        a += __shfl_xor_sync(0xFFFFFFFFu, a, 4);
        if (q == 0) g_const[n * 16 + k] = a;
    } else {                             // s_n = b1 . u_n, 16 threads per n
        int o2 = t - 448;
        int n = o2 >> 4, q = o2 & 15;
        float a = 0.f;
        #pragma unroll
        for (int i = 0; i < 8; ++i)
            a = fmaf(b1[q * 8 + i], us_s[n * 128 + q * 8 + i], a);
        a += __shfl_xor_sync(0xFFFFFFFFu, a, 1);
        a += __shfl_xor_sync(0xFFFFFFFFu, a, 2);
        a += __shfl_xor_sync(0xFFFFFFFFu, a, 4);
        a += __shfl_xor_sync(0xFFFFFFFFu, a, 8);
        if (q == 0) g_const[64 + n] = a;
    }

    // C: bias chain + b2 term
    __syncthreads();
    if (t < 256)
        part[t] = bl1[t]*t2s[t] + bl2[t]*t1s[t] + (bl3[t]+bl1[t])*w4s[t]
                + b2[t & 63]*Mss[t];
    __syncthreads();
    #pragma unroll
    for (int s = 128; s > 0; s >>= 1) {
        if (t < s) part[t] += part[t + s];
        __syncthreads();
    }
    if (t == 0) g_const[68] = part[0] + bl4[0];
}

// ---------------------------------------------------------------------------
// Main kernel: 1 thread per graph. Edges staged + consumed first, then x is
// staged into the SAME smem region (union) -> smem 61.8KB -> 3 blocks/SM.
//   region0 @0 (61440B): first es4 int4[1792], then xs4 float4[3840]
//   cs @61440 (320B)
// ---------------------------------------------------------------------------
#define SMEM_CS 61440
#define SMEM_TOTAL 61760

__global__ void __launch_bounds__(TPB, 3) gnn_kernel(
    const float* __restrict__ x, const int* __restrict__ ei,
    float* __restrict__ out)
{
    extern __shared__ unsigned char smem[];
    float4* xs4 = (float4*)smem;
    int4*   es4 = (int4*)smem;
    float*  cs  = (float*)(smem + SMEM_CS);

    const int t = threadIdx.x;
    const long long gbase = (long long)blockIdx.x * GPB;

    if (t < 80) cs[t] = g_const[t];

    // stage edges: 256 graphs * 6 int4, coalesced loads, odd-stride stores
    const int4* eg = (const int4*)(ei + gbase * 24);
    #pragma unroll
    for (int j0 = 0; j0 < 6; ++j0) {
        int i4 = t + j0 * 256;
        int4 v = eg[i4];
        int g = i4 / 6;
        int j = i4 - g * 6;
        es4[g * 7 + j] = v;
    }
    __syncthreads();

    // my graph's edges: 6 conflict-free LDS.128 -> registers
    int me[24];
    #pragma unroll
    for (int j = 0; j < 6; ++j) {
        int4 e = es4[t * 7 + j];
        me[j*4+0] = e.x; me[j*4+1] = e.y; me[j*4+2] = e.z; me[j*4+3] = e.w;
    }
    __syncthreads();   // all edge reads done before x overwrites region0

    // stage x: 256 graphs * 14 float4, coalesced loads, odd-stride stores
    const float4* xg = (const float4*)(x + gbase * 56);
    #pragma unroll
    for (int j0 = 0; j0 < 14; ++j0) {
        int i4 = t + j0 * 256;
        float4 v = xg[i4];
        int g = i4 / 14;
        int j = i4 - g * 14;
        xs4[g * 15 + j] = v;
    }

    // --- meanwhile (pre-sync): build A, A2, coefficient vector g[] ---
    unsigned long long accm = 0ull;
    #pragma unroll
    for (int e = 0; e < 12; ++e) {
        int s = me[e];
        int d = me[12 + e];
        accm += 1ull << (((d << 2) + s) << 2);
    }

    float dinv[4];
    #pragma unroll
    for (int n = 0; n < 4; ++n) {
        unsigned int rown = (unsigned int)(accm >> (16 * n)) & 0xFFFFu;
        int deg = 1 + (rown & 15) + ((rown >> 4) & 15)
                    + ((rown >> 8) & 15) + ((rown >> 12) & 15);
        dinv[n] = c_rsq[deg];
    }

    float A[16];
    #pragma unroll
    for (int n = 0; n < 4; ++n) {
        #pragma unroll
        for (int m = 0; m < 4; ++m) {
            int cnt = (int)((accm >> (4 * (n * 4 + m))) & 15ull) + (n == m);
            A[n * 4 + m] = dinv[n] * dinv[m] * (float)cnt;
        }
    }

    float acc = cs[68];
    #pragma unroll
    for (int n = 0; n < 4; ++n)
        acc = fmaf(A[n*4] + A[n*4+1] + A[n*4+2] + A[n*4+3], cs[64 + n], acc);

    float A2[16];
    #pragma unroll
    for (int n = 0; n < 4; ++n) {
        #pragma unroll
        for (int m = 0; m < 4; ++m) {
            A2[n*4+m] = fmaf(A[n*4+0], A[0*4+m],
                        fmaf(A[n*4+1], A[1*4+m],
                        fmaf(A[n*4+2], A[2*4+m], A[n*4+3] * A[3*4+m])));
        }
    }

    // g[e] for x element e (m = e/14, k = e%14): g = sum_n A2[n][m]*v_n[k]
    float g[56];
    #pragma unroll
    for (int e = 0; e < 56; ++e) {
        const int m = e / 14, k = e - 14 * m;
        g[e] = fmaf(A2[0*4+m], cs[0*16+k],
               fmaf(A2[1*4+m], cs[1*16+k],
               fmaf(A2[2*4+m], cs[2*16+k], A2[3*4+m] * cs[3*16+k])));
    }
    __syncthreads();

    // stream my graph's features: 14 conflict-free LDS.128, consume directly
    #pragma unroll
    for (int j = 0; j < 14; ++j) {
        float4 v = xs4[t * 15 + j];
        const int e = 4 * j;
        acc = fmaf(v.x, g[e+0], fmaf(v.y, g[e+1],
              fmaf(v.z, g[e+2], fmaf(v.w, g[e+3], acc))));
    }
    out[gbase + t] = acc;
}

// ---------------------------------------------------------------------------
extern "C" void kernel_launch(void* const* d_in, const int* in_sizes, int n_in,
                              void* d_out, int out_size)
{
    const float* x   = (const float*)d_in[0];
    const int*   ei  = (const int*)  d_in[1];
    const float* W1  = (const float*)d_in[2];
    const float* b1  = (const float*)d_in[3];
    const float* W2  = (const float*)d_in[4];
    const float* b2  = (const float*)d_in[5];
    const float* Wl1 = (const float*)d_in[6];
    const float* bl1 = (const float*)d_in[7];
    const float* Wl2 = (const float*)d_in[8];
    const float* bl2 = (const float*)d_in[9];
    const float* Wl3 = (const float*)d_in[10];
    const float* bl3 = (const float*)d_in[11];
    const float* Wl4 = (const float*)d_in[12];
    const float* bl4 = (const float*)d_in[13];

    const int B = in_sizes[0] / 56;          // 262144
    const int nblocks = B / GPB;             // 1024

    float* t1; cudaGetSymbolAddress((void**)&t1, g_t1);
    float* t2; cudaGetSymbolAddress((void**)&t2, g_t2);
    float* Ms; cudaGetSymbolAddress((void**)&Ms, g_Ms);

    mv256_kernel<<<32, 256>>>(Wl3, Wl4, t1);             // t1 = Wl3 @ w4
    mv256_kernel<<<32, 256>>>(Wl2, t1,  t2);             // t2 = Wl2 @ t1
    mv256_dual_kernel<<<32, 256>>>(Wl1, t2, Wl4, Ms);    // M = Wl1 t2 + Wl1 w4 + w4
    u_kernel<<<8, 256>>>(W2);                            // u_n = W2 m_n
    finish_kernel<<<1, 512>>>(W1, b1, b2, bl1, bl2, bl3, Wl4, bl4);

    cudaFuncSetAttribute(gnn_kernel,
                         cudaFuncAttributeMaxDynamicSharedMemorySize, SMEM_TOTAL);
    gnn_kernel<<<nblocks, TPB, SMEM_TOTAL>>>(x, ei, (float*)d_out);
}